// round 17
// baseline (speedup 1.0000x reference)
#include <cuda_runtime.h>
#include <cuda_fp16.h>
#include <cstdint>

// ---------------------------------------------------------------------------
// MultiHeadSelfAttention: B=2, T=2048, D=1024, H=16, DK=64
// R17: PV switches to CHUNKED f16-accumulate (f16 chain within a KV tile,
// fp32 master accumulator across tiles) — R16 confirmed fp32-acc HMMA runs
// at half rate. Row sums via __hadd2 trees. GEMMs stay fp32-acc (error
// ledger forbids whole-K f16 chains there). Fused dataflow from R14.
// ---------------------------------------------------------------------------

#define B_   2
#define T_   2048
#define D_   1024
#define H_   16
#define DK_  64
#define M_   (B_ * T_)      // 4096
#define D3_  (3 * D_)       // 3072

#define QSCALE 0.18033688011112042f   // 0.125 * log2(e)

#define N_G1   768
#define N_AT   512
#define N_OP   256
#define N_TOT  (N_G1 + N_AT + N_OP)

__device__ __align__(16) __half g_qkvh[(size_t)M_ * D3_];
__device__ __align__(16) __half g_xh  [(size_t)M_ * D_];
__device__ __align__(16) __half g_wqth[(size_t)D3_ * D_];
__device__ __align__(16) __half g_woth[(size_t)D_ * D_];
__device__ __align__(16) __half g_ath [(size_t)M_ * D_];

__device__ int g_flag[N_G1];
__device__ int g_acnt[32];

// ---------------------------------------------------------------------------
__device__ __forceinline__ uint32_t smem_to_u32(const void* p) {
    uint32_t a;
    asm("{ .reg .u64 t; cvta.to.shared.u64 t, %1; cvt.u32.u64 %0, t; }"
        : "=r"(a) : "l"(p));
    return a;
}

#define CP_ASYNC16(sa, ga) \
    asm volatile("cp.async.cg.shared.global [%0], [%1], 16;" :: "r"(sa), "l"(ga))
#define CP_COMMIT() asm volatile("cp.async.commit_group;" ::: "memory")
#define CP_WAIT0()  asm volatile("cp.async.wait_group 0;" ::: "memory")

#define LDMX4(r0, r1, r2, r3, addr) \
    asm volatile("ldmatrix.sync.aligned.m8n8.x4.shared.b16 {%0,%1,%2,%3}, [%4];" \
        : "=r"(r0), "=r"(r1), "=r"(r2), "=r"(r3) : "r"(addr))
#define LDMX4T(r0, r1, r2, r3, addr) \
    asm volatile("ldmatrix.sync.aligned.m8n8.x4.trans.shared.b16 {%0,%1,%2,%3}, [%4];" \
        : "=r"(r0), "=r"(r1), "=r"(r2), "=r"(r3) : "r"(addr))

// fp32-accumulate (GEMMs)
#define MMA_F16(d, a, b0, b1) \
    asm volatile("mma.sync.aligned.m16n8k16.row.col.f32.f16.f16.f32 " \
        "{%0,%1,%2,%3}, {%4,%5,%6,%7}, {%8,%9}, {%0,%1,%2,%3};" \
        : "+f"((d)[0]), "+f"((d)[1]), "+f"((d)[2]), "+f"((d)[3]) \
        : "r"((a)[0]), "r"((a)[1]), "r"((a)[2]), "r"((a)[3]), "r"(b0), "r"(b1))

// f16-accumulate (attention QK^T and PV): C fragment = 2 packed f16x2 regs
#define MMA_F16ACC(d0, d1, a, b0, b1) \
    asm volatile("mma.sync.aligned.m16n8k16.row.col.f16.f16.f16.f16 " \
        "{%0,%1}, {%2,%3,%4,%5}, {%6,%7}, {%0,%1};" \
        : "+r"(d0), "+r"(d1) \
        : "r"((a)[0]), "r"((a)[1]), "r"((a)[2]), "r"((a)[3]), "r"(b0), "r"(b1))

#define EX2H2(y, x) asm("ex2.approx.f16x2 %0, %1;" : "=r"(y) : "r"(x))

__device__ __forceinline__ uint32_t pack_f16(float lo, float hi) {
    __half2 p;
    p.x = __float2half(lo);
    p.y = __float2half(hi);
    return *reinterpret_cast<uint32_t*>(&p);
}
__device__ __forceinline__ uint32_t hadd2u(uint32_t a, uint32_t b) {
    uint32_t r;
    asm("add.f16x2 %0, %1, %2;" : "=r"(r) : "r"(a), "r"(b));
    return r;
}
__device__ __forceinline__ float2 h2f2(uint32_t u) {
    return __half22float2(*reinterpret_cast<__half2*>(&u));
}

__device__ __forceinline__ void wait_flag(const int* p) {
    int v;
    while (true) {
        asm volatile("ld.acquire.gpu.global.u32 %0, [%1];"
                     : "=r"(v) : "l"(p) : "memory");
        if (v != 0) break;
        __nanosleep(64);
    }
}
__device__ __forceinline__ void wait_cnt(const int* p, int tgt) {
    int v;
    while (true) {
        asm volatile("ld.acquire.gpu.global.u32 %0, [%1];"
                     : "=r"(v) : "l"(p) : "memory");
        if (v >= tgt) break;
        __nanosleep(128);
    }
}

// ---------------------------------------------------------------------------
// prep
// ---------------------------------------------------------------------------
__device__ __forceinline__ void transpose_body(const float* __restrict__ W,
                                               __half* __restrict__ Th,
                                               int K, int N, int bx, int by,
                                               int tid, float (*t)[33])
{
    int tx = tid & 31, ty = tid >> 5;
    int n0 = bx * 32, k0 = by * 32;
#pragma unroll
    for (int j = ty; j < 32; j += 8)
        t[j][tx] = W[(size_t)(k0 + j) * N + n0 + tx];
    __syncthreads();
#pragma unroll
    for (int j = ty; j < 32; j += 8)
        Th[(size_t)(n0 + j) * K + k0 + tx] = __float2half(t[tx][j]);
}

__global__ void prep_kernel(const float* __restrict__ x,
                            const float* __restrict__ Wqkv,
                            const float* __restrict__ Wout)
{
    __shared__ float t[32][33];
    const int bid = blockIdx.x;
    const int tid = threadIdx.x;
    if (bid < 4096) {
        int i = bid * 256 + tid;
        float4 v = ((const float4*)x)[i];
        ((uint32_t*)g_xh)[i * 2]     = pack_f16(v.x, v.y);
        ((uint32_t*)g_xh)[i * 2 + 1] = pack_f16(v.z, v.w);
    } else if (bid < 4096 + 3072) {
        int f = bid - 4096;
        transpose_body(Wqkv, g_wqth, D_, D3_, f % 96, f / 96, tid, t);
    } else if (bid < 8192) {
        int f = bid - 7168;
        transpose_body(Wout, g_woth, D_, D_, f % 32, f / 32, tid, t);
    } else {
        for (int i = tid; i < N_G1; i += 256) g_flag[i] = 0;
        if (tid < 32) g_acnt[tid] = 0;
        __threadfence();
    }
}

// ---------------------------------------------------------------------------
// GEMM body (fp32 acc, unchanged)
// ---------------------------------------------------------------------------
#define BK          64
#define TSTRIDE     144
#define TILE_BYTES  (128 * TSTRIDE)
#define STG_BYTES   (2 * TILE_BYTES)
#define FUSE_SMEM   (2 * STG_BYTES)

__device__ __forceinline__ void gemm_body(
    const __half* __restrict__ Ah, const __half* __restrict__ Bh,
    const float* __restrict__ bias, float* __restrict__ C,
    __half* __restrict__ Ch, int qcols, int Ndim, int Kdim,
    int m0, int n0, char* sm)
{
    const uint32_t sbase = smem_to_u32(sm);
    const int tid  = threadIdx.x;
    const int lane = tid & 31;
    const int w    = tid >> 5;
    const int wm   = w >> 2;
    const int wn   = w & 3;

    const __half* srcs[2] = {
        Ah + (size_t)m0 * Kdim, Bh + (size_t)n0 * Kdim };

    const int lrow = (lane & 7) + ((lane >> 3) & 1) * 8;
    const uint32_t lmoff = (uint32_t)(lrow * TSTRIDE + (lane >> 4) * 16);

    float acc[4][4][4];
#pragma unroll
    for (int mf = 0; mf < 4; mf++)
#pragma unroll
        for (int nf = 0; nf < 4; nf++)
#pragma unroll
            for (int e = 0; e < 4; e++) acc[mf][nf][e] = 0.f;

    auto load_chunk = [&](int c, int stg) {
        const int k0 = c * BK;
        const uint32_t bb = sbase + stg * STG_BYTES;
#pragma unroll
        for (int t = 0; t < 2; t++) {
#pragma unroll
            for (int it = 0; it < 4; it++) {
                int idx = tid + it * 256;
                int r = idx >> 3, ch = idx & 7;
                CP_ASYNC16(bb + t * TILE_BYTES + r * TSTRIDE + ch * 16,
                           srcs[t] + (size_t)r * Kdim + k0 + ch * 8);
            }
        }
        CP_COMMIT();
    };

    const int nchunks = Kdim / BK;
    load_chunk(0, 0);

    for (int c = 0; c < nchunks; c++) {
        const int buf = c & 1;
        CP_WAIT0();
        __syncthreads();
        if (c + 1 < nchunks) load_chunk(c + 1, buf ^ 1);

        const uint32_t tb = sbase + buf * STG_BYTES;
#pragma unroll
        for (int s = 0; s < 4; s++) {
            const uint32_t koff = s * 32;
            uint32_t ah[4][4];
#pragma unroll
            for (int mf = 0; mf < 4; mf++) {
                uint32_t ra = tb + (uint32_t)((wm * 64 + mf * 16) * TSTRIDE)
                            + koff + lmoff;
                LDMX4(ah[mf][0], ah[mf][1], ah[mf][2], ah[mf][3], ra);
            }
#pragma unroll
            for (int nh = 0; nh < 2; nh++) {
                uint32_t rb = tb + TILE_BYTES
                            + (uint32_t)((wn * 32 + nh * 16) * TSTRIDE)
                            + koff + lmoff;
                uint32_t bh[4];
                LDMX4(bh[0], bh[1], bh[2], bh[3], rb);
#pragma unroll
                for (int nf2 = 0; nf2 < 2; nf2++) {
                    const int nf = nh * 2 + nf2;
#pragma unroll
                    for (int mf = 0; mf < 4; mf++)
                        MMA_F16(acc[mf][nf], ah[mf], bh[nf2], bh[nf2 + 2]);
                }
            }
        }
    }

    const int g  = lane >> 2;
    const int t2 = (lane & 3) * 2;
#pragma unroll
    for (int mf = 0; mf < 4; mf++) {
        const int row = m0 + wm * 64 + mf * 16 + g;
#pragma unroll
        for (int nf = 0; nf < 4; nf++) {
            const int col = n0 + wn * 32 + nf * 8 + t2;
            float b0 = __ldg(bias + col), b1 = __ldg(bias + col + 1);
            float v00 = acc[mf][nf][0] + b0, v01 = acc[mf][nf][1] + b1;
            float v10 = acc[mf][nf][2] + b0, v11 = acc[mf][nf][3] + b1;
            if (Ch) {
                float sc = (col < qcols) ? QSCALE : 1.0f;
                size_t o0 = (size_t)row * Ndim + col;
                size_t o1 = (size_t)(row + 8) * Ndim + col;
                *(uint32_t*)(Ch + o0) = pack_f16(v00 * sc, v01 * sc);
                *(uint32_t*)(Ch + o1) = pack_f16(v10 * sc, v11 * sc);
            } else {
                float2 w0, w1;
                w0.x = v00; w0.y = v01;
                w1.x = v10; w1.y = v11;
                *(float2*)(C + (size_t)row * Ndim + col)       = w0;
                *(float2*)(C + (size_t)(row + 8) * Ndim + col) = w1;
            }
        }
    }
}

// ---------------------------------------------------------------------------
// Attention body: QK^T f16-acc; PV CHUNKED f16-acc (f16 within tile, fp32
// across tiles); __hadd2-tree row sums. Dataflow waits as R14.
// ---------------------------------------------------------------------------
#define KV      64
#define AST     144
#define TEN_B   (KV * AST)
#define ABUF    (2 * TEN_B)

__device__ __forceinline__ void attn_body(int a, const __half* __restrict__ qkvh,
                                          __half* __restrict__ outh, char* sm)
{
    const uint32_t sb = smem_to_u32(sm);
    const int tid  = threadIdx.x;
    const int lane = tid & 31;
    const int w    = tid >> 5;

    const int qi = a >> 4;
    const int h  = a & 15;
    const int b  = qi >> 4;
    const int q0 = (qi & 15) * 128;
    const int hc = h >> 1;

    const __half* baseh = qkvh + (size_t)b * T_ * D3_;

    const int g  = lane >> 2;
    const int t2 = (lane & 3) * 2;
    const int lrow = (lane & 7) + ((lane >> 3) & 1) * 8;
    const uint32_t lmcol = (uint32_t)((lane >> 4) * 16);
    const int vtok = (lane & 7) + ((lane >> 4) & 1) * 8;
    const uint32_t vdk16 = (uint32_t)(((lane >> 3) & 1) * 16);

    if (tid == 0) {
        wait_flag(&g_flag[qi * 24 + hc]);
        wait_flag(&g_flag[(b * 16) * 24 + 8 + hc]);
        wait_flag(&g_flag[(b * 16) * 24 + 16 + hc]);
    }
    __syncthreads();

#pragma unroll
    for (int i = tid; i < 1024; i += 256) {
        int row = i >> 3, ch = i & 7;
        const __half* src = baseh + (size_t)(q0 + row) * D3_ + h * DK_ + ch * 8;
        CP_ASYNC16(sb + row * AST + ch * 16, src);
    }
    CP_COMMIT(); CP_WAIT0();
    __syncthreads();

    uint32_t qf[4][4];
#pragma unroll
    for (int kc = 0; kc < 4; kc++) {
        uint32_t ra = sb + (uint32_t)((w * 16 + lrow) * AST) + kc * 32 + lmcol;
        LDMX4(qf[kc][0], qf[kc][1], qf[kc][2], qf[kc][3], ra);
    }
    __syncthreads();

    auto load_kv = [&](int t, int buf) {
        const int k0 = t * KV;
        const uint32_t bb = sb + buf * ABUF;
        const __half* srcs[2] = {
            baseh + D_ + h * DK_, baseh + 2 * D_ + h * DK_ };
#pragma unroll
        for (int i = tid; i < 1024; i += 256) {
            int ten = i >> 9, rem = i & 511;
            int row = rem >> 3, ch = rem & 7;
            CP_ASYNC16(bb + ten * TEN_B + row * AST + ch * 16,
                       srcs[ten] + (size_t)(k0 + row) * D3_ + ch * 8);
        }
        CP_COMMIT();
    };

    float l0 = 0.f, l1 = 0.f;
    float oacc[8][4];
#pragma unroll
    for (int j = 0; j < 8; j++)
#pragma unroll
        for (int e = 0; e < 4; e++) oacc[j][e] = 0.f;

    const int ntiles = T_ / KV;          // 32
    load_kv(0, 0);

    for (int t = 0; t < ntiles; t++) {
        const int buf = t & 1;
        CP_WAIT0();
        if (tid == 0 && t + 1 < ntiles) {
            int mtv = b * 16 + ((t + 1) >> 1);
            wait_flag(&g_flag[mtv * 24 + 8 + hc]);
            wait_flag(&g_flag[mtv * 24 + 16 + hc]);
        }
        __syncthreads();
        if (t + 1 < ntiles) load_kv(t + 1, buf ^ 1);
        const uint32_t kb = sb + buf * ABUF;

        // S' = (log2e/8 * Q) K^T  -- f16 accumulate
        uint32_t sfh[8][2];
#pragma unroll
        for (int nt = 0; nt < 8; nt++) { sfh[nt][0] = 0u; sfh[nt][1] = 0u; }

#pragma unroll
        for (int p = 0; p < 4; p++) {
#pragma unroll
            for (int kc = 0; kc < 4; kc++) {
                uint32_t rb = kb + (uint32_t)((p * 16 + lrow) * AST)
                            + kc * 32 + lmcol;
                uint32_t kh[4];
                LDMX4(kh[0], kh[1], kh[2], kh[3], rb);
                MMA_F16ACC(sfh[2 * p][0],     sfh[2 * p][1],
                           qf[kc], kh[0], kh[2]);
                MMA_F16ACC(sfh[2 * p + 1][0], sfh[2 * p + 1][1],
                           qf[kc], kh[1], kh[3]);
            }
        }

        // P = 2^{S'} in f16x2; row sums via hadd2 tree (fp32 master l)
#pragma unroll
        for (int nt = 0; nt < 8; nt++) {
            EX2H2(sfh[nt][0], sfh[nt][0]);
            EX2H2(sfh[nt][1], sfh[nt][1]);
        }
        {
            uint32_t s0 = hadd2u(hadd2u(hadd2u(sfh[0][0], sfh[1][0]),
                                        hadd2u(sfh[2][0], sfh[3][0])),
                                 hadd2u(hadd2u(sfh[4][0], sfh[5][0]),
                                        hadd2u(sfh[6][0], sfh[7][0])));
            uint32_t s1 = hadd2u(hadd2u(hadd2u(sfh[0][1], sfh[1][1]),
                                        hadd2u(sfh[2][1], sfh[3][1])),
                                 hadd2u(hadd2u(sfh[4][1], sfh[5][1]),
                                        hadd2u(sfh[6][1], sfh[7][1])));
            float2 f0 = h2f2(s0), f1 = h2f2(s1);
            l0 += f0.x + f0.y;
            l1 += f1.x + f1.y;
        }

        // O += P V  -- f16 accumulate within the tile, fp32 across tiles
        uint32_t facc[4][4];
#pragma unroll
        for (int dp = 0; dp < 4; dp++)
#pragma unroll
            for (int j = 0; j < 4; j++) facc[dp][j] = 0u;

#pragma unroll
        for (int kf = 0; kf < 4; kf++) {
            uint32_t pa[4];
            pa[0] = sfh[2 * kf][0];
            pa[1] = sfh[2 * kf][1];
            pa[2] = sfh[2 * kf + 1][0];
            pa[3] = sfh[2 * kf + 1][1];
#pragma unroll
            for (int dp = 0; dp < 4; dp++) {
                uint32_t va = kb + TEN_B
                            + (uint32_t)((kf * 16 + vtok) * AST)
                            + dp * 32 + vdk16;
                uint32_t vh[4];
                LDMX4T(vh[0], vh[1], vh[2], vh[3], va);
                MMA_F16ACC(facc[dp][0], facc[dp][1], pa, vh[0], vh[2]);
                MMA_F16ACC(facc[dp][2], facc[dp][3], pa, vh[1], vh[3]);
            }
        }
        // spill tile partials into fp32 master accumulator
#pragma unroll
        for (int dp = 0; dp < 4; dp++) {
            float2 f;
            f = h2f2(facc[dp][0]); oacc[2 * dp][0] += f.x; oacc[2 * dp][1] += f.y;
            f = h2f2(facc[dp][1]); oacc[2 * dp][2] += f.x; oacc[2 * dp][3] += f.y;
            f = h2f2(facc[dp][2]); oacc[2 * dp + 1][0] += f.x; oacc[2 * dp + 1][1] += f.y;
            f = h2f2(facc[dp][3]); oacc[2 * dp + 1][2] += f.x; oacc[2 * dp + 1][3] += f.y;
        }
    }

    l0 += __shfl_xor_sync(0xffffffffu, l0, 1);
    l0 += __shfl_xor_sync(0xffffffffu, l0, 2);
    l1 += __shfl_xor_sync(0xffffffffu, l1, 1);
    l1 += __shfl_xor_sync(0xffffffffu, l1, 2);

    const float inv0 = 1.f / l0, inv1 = 1.f / l1;
    const size_t r0 = (size_t)(b * T_ + q0 + w * 16 + g) * D_ + h * DK_;
    const size_t r1 = r0 + 8 * D_;
#pragma unroll
    for (int j = 0; j < 8; j++) {
        *(uint32_t*)(outh + r0 + j * 8 + t2) =
            pack_f16(oacc[j][0] * inv0, oacc[j][1] * inv0);
        *(uint32_t*)(outh + r1 + j * 8 + t2) =
            pack_f16(oacc[j][2] * inv1, oacc[j][3] * inv1);
    }
}

// ---------------------------------------------------------------------------
__global__ __launch_bounds__(256, 2)
void fused_kernel(float* __restrict__ out,
                  const float* __restrict__ bqkv,
                  const float* __restrict__ bout)
{
    extern __shared__ char sm[];
    const int bid = blockIdx.x;
    const int tid = threadIdx.x;

    if (bid < N_G1) {
        const int mt = bid / 24, nt = bid % 24;
        gemm_body(g_xh, g_wqth, bqkv, nullptr, g_qkvh,
                  D_, D3_, D_, mt * 128, nt * 128, sm);
        __threadfence();
        __syncthreads();
        if (tid == 0) atomicExch(&g_flag[bid], 1);
    } else if (bid < N_G1 + N_AT) {
        const int a = bid - N_G1;
        attn_body(a, g_qkvh, g_ath, sm);
        __threadfence();
        __syncthreads();
        if (tid == 0) atomicAdd(&g_acnt[a >> 4], 1);
    } else {
        const int o = bid - N_G1 - N_AT;
        const int mt = o >> 3, nt = o & 7;
        if (tid == 0) wait_cnt(&g_acnt[mt], 16);
        __syncthreads();
        gemm_body(g_ath, g_woth, bout, out, nullptr,
                  0, D_, D_, mt * 128, nt * 128, sm);
    }
}

// ---------------------------------------------------------------------------
extern "C" void kernel_launch(void* const* d_in, const int* in_sizes, int n_in,
                              void* d_out, int out_size)
{
    const float* x    = (const float*)d_in[0];
    const float* Wqkv = (const float*)d_in[1];
    const float* bqkv = (const float*)d_in[2];
    const float* Wout = (const float*)d_in[3];
    const float* bout = (const float*)d_in[4];
    float*       out  = (float*)d_out;

    cudaFuncSetAttribute(fused_kernel,
                         cudaFuncAttributeMaxDynamicSharedMemorySize, FUSE_SMEM);

    prep_kernel<<<8193, 256>>>(x, Wqkv, Wout);
    fused_kernel<<<N_TOT, 256, FUSE_SMEM>>>(out, bqkv, bout);
}